// round 7
// baseline (speedup 1.0000x reference)
#include <cuda_runtime.h>
#include <cuda_bf16.h>
#include <cstdint>
#include <math.h>

#define VOCAB 32000
#define DMODEL 256
#define NREP 16
#define NLAYER 6
#define DS 16
#define DC 4
#define DI 512
#define DTR 16
#define NH 4
#define HD 64
#define LSEQ 128
#define ROWS (NREP*LSEQ)   // 2048
#define XDW 48             // DTR + 2*DS
#define KSPLIT 4

// ---------------- scratch (device globals; no allocation allowed) ----------
__device__ float g_h[ROWS*DMODEL];          // residual stream [n*128+l, 256]
__device__ float g_z[ROWS*DI];              // z half of in_proj
__device__ float g_u[ROWS*DI];              // conv+silu out
__device__ float g_xdbl[KSPLIT*ROWS*XDW];   // split-K partials of u @ xpw^T
__device__ float g_gate[ROWS*DI];           // y * silu(z)
__device__ float g_qkv[ROWS*3*DMODEL];      // [2048,768] rows l*16+n
__device__ float g_attno[ROWS*DMODEL];      // attention o (pre out-proj)
__device__ float g_hf[LSEQ*DMODEL];         // mean + final LN

// ---------------- helpers ----------
__device__ __forceinline__ float siluf(float x) {
    return x / (1.f + __expf(-x));
}
__device__ __forceinline__ float softplusf(float x) {
    return (x > 20.f) ? x : log1pf(__expf(x));
}

__device__ __forceinline__ uint32_t packbf(float x, float y) {
    __nv_bfloat162 h = __floats2bfloat162_rn(x, y);
    return *reinterpret_cast<uint32_t*>(&h);
}

// bf16 m16n8k16 mma, fp32 accumulate
__device__ __forceinline__ void mma16(float* c, const uint32_t* a, const uint32_t* b) {
    asm volatile(
        "mma.sync.aligned.m16n8k16.row.col.f32.bf16.bf16.f32 "
        "{%0,%1,%2,%3}, {%4,%5,%6,%7}, {%8,%9}, {%0,%1,%2,%3};"
        : "+f"(c[0]), "+f"(c[1]), "+f"(c[2]), "+f"(c[3])
        : "r"(a[0]), "r"(a[1]), "r"(a[2]), "r"(a[3]), "r"(b[0]), "r"(b[1]));
}

__device__ float blockReduceSum256(float v) {
    __shared__ float s[8];
    __shared__ float tot;
    int lane = threadIdx.x & 31, wid = threadIdx.x >> 5;
    #pragma unroll
    for (int o = 16; o > 0; o >>= 1) v += __shfl_xor_sync(0xffffffffu, v, o);
    if (lane == 0) s[wid] = v;
    __syncthreads();
    if (wid == 0) {
        float w = (lane < 8) ? s[lane] : 0.f;
        #pragma unroll
        for (int o = 4; o > 0; o >>= 1) w += __shfl_xor_sync(0xffffffffu, w, o);
        if (lane == 0) tot = w;
    }
    __syncthreads();
    float r = tot;
    __syncthreads();
    return r;
}

// ---------------- kernels ----------

__global__ void k_embed(const int* __restrict__ x, const float* __restrict__ emb) {
    int idx = blockIdx.x * blockDim.x + threadIdx.x;       // 16*128*256
    if (idx >= ROWS*DMODEL) return;
    int d = idx & (DMODEL-1);
    int r = idx >> 8;           // n*128+l
    int l = r & (LSEQ-1);
    g_h[idx] = emb[(size_t)x[l]*DMODEL + d];
}

// replica mean + final LayerNorm. grid = LSEQ, block = 256.
__global__ void k_meanln(const float* __restrict__ w, const float* __restrict__ b) {
    int l = blockIdx.x;
    int d = threadIdx.x;
    float v = 0.f;
    #pragma unroll
    for (int n = 0; n < NREP; n++) v += g_h[(size_t)((n<<7)+l)*DMODEL + d];
    v *= (1.f/NREP);
    float m = blockReduceSum256(v) * (1.f/DMODEL);
    float c = v - m;
    float var = blockReduceSum256(c*c) * (1.f/DMODEL);
    g_hf[(size_t)l*DMODEL + d] = c * rsqrtf(var + 1e-5f) * w[d] + b[d];
}

// ---------------- tensor-core split-bf16 GEMM (near-fp32 accurate) --------
// C[M,N] = act(A[M,K] @ W[N,K]^T + bias)
// mode: 0 = store, 1 = +=, 2 = permuted += (row l*16+n -> n*128+l)
// mode 3 = in_proj special (BM=128): n0<DI -> fused causal conv+silu -> uout;
//          n0>=DI -> store z half to zout (compact DI-wide).
// lnmode: 0 none; 1 = LayerNorm A rows; 2 = LayerNorm A rows with permuted read
//         (logical row gm=l*16+n reads h row n*128+l). K must equal LN dim.
// split-K: gridDim.z>1 shifts A,W by z*K cols and C by z*M*ldc.
#define TBN 64
#define TBK 16
#define SW 12           // padded words per row (8 data + 4 pad)
template<int BM>
__global__ void __launch_bounds__(BM*2)
k_gemm_tc(const float* __restrict__ A, int lda,
          const float* __restrict__ W, int ldw,
          const float* __restrict__ bias,
          float* __restrict__ C, int ldc,
          int M, int N, int K, int act, int mode,
          const float* __restrict__ lnw, const float* __restrict__ lnb, int lnmode,
          const float* __restrict__ cvw, const float* __restrict__ cvb,
          float* __restrict__ uout, float* __restrict__ zout) {
    constexpr int T = BM*2;                  // 256 or 128 threads
    constexpr int AW = 2*BM*SW;
    constexpr int WW = 2*TBN*SW;
    __shared__ __align__(16) uint32_t smem[2*AW + 2*WW];
    __shared__ float sMean[BM], sRstd[BM];
    uint32_t* Ash = smem;
    uint32_t* Asl = smem + AW;
    uint32_t* Wsh = smem + 2*AW;
    uint32_t* Wsl = smem + 2*AW + WW;
    #define ASH(s,m,k) Ash[((s)*BM+(m))*SW+(k)]
    #define ASL(s,m,k) Asl[((s)*BM+(m))*SW+(k)]
    #define WSH(s,n,k) Wsh[((s)*TBN+(n))*SW+(k)]
    #define WSL(s,n,k) Wsl[((s)*TBN+(n))*SW+(k)]

    int tid = threadIdx.x;
    int wid = tid >> 5, lane = tid & 31;
    int wm = wid >> 1, wn = wid & 1;
    int g = lane >> 2, t = lane & 3;
    int m0 = blockIdx.y * BM, n0 = blockIdx.x * TBN;

    // split-K offsets
    if (gridDim.z > 1) {
        A += (size_t)blockIdx.z * K;
        W += (size_t)blockIdx.z * K;
        C += (size_t)blockIdx.z * M * ldc;
    }

    // optional LN prologue: row stats for this block's BM rows
    if (lnmode) {
        constexpr int NWARP = T/32;
        for (int r = wid; r < BM; r += NWARP) {
            int gm = m0 + r;
            int row = (lnmode == 2) ? (((gm & 15) << 7) + (gm >> 4)) : gm;
            float s = 0.f, s2 = 0.f;
            for (int k = lane*4; k < K; k += 128) {
                float4 v = *reinterpret_cast<const float4*>(&A[(size_t)row*lda + k]);
                s  += v.x + v.y + v.z + v.w;
                s2 += v.x*v.x + v.y*v.y + v.z*v.z + v.w*v.w;
            }
            #pragma unroll
            for (int o = 16; o > 0; o >>= 1) {
                s  += __shfl_xor_sync(0xffffffffu, s, o);
                s2 += __shfl_xor_sync(0xffffffffu, s2, o);
            }
            if (lane == 0) {
                float mean = s / K;
                float var = s2 / K - mean*mean;
                sMean[r] = mean;
                sRstd[r] = rsqrtf(var + 1e-5f);
            }
        }
        __syncthreads();
    }

    float acc[2][4][4] = {};
    constexpr int NA4 = BM*4/T;   // per-thread A float4 count (=2)
    constexpr int NW4 = TBN*4/T;  // per-thread W float4 count (1 or 2)
    float4 rA[NA4], rW[NW4 ? NW4 : 1];

    auto load_tile = [&](int k0) {
        #pragma unroll
        for (int i = 0; i < NA4; i++) {
            int slot = tid + i*T;
            int m = slot >> 2;
            int gm = m0 + m, gk = k0 + (slot & 3)*4;
            float4 v = make_float4(0.f,0.f,0.f,0.f);
            if (gm < M && gk < K) {
                int row = (lnmode == 2) ? (((gm & 15) << 7) + (gm >> 4)) : gm;
                if (gk + 3 < K) v = *reinterpret_cast<const float4*>(&A[(size_t)row*lda + gk]);
                else {
                    v.x = A[(size_t)row*lda+gk];
                    if (gk+1 < K) v.y = A[(size_t)row*lda+gk+1];
                    if (gk+2 < K) v.z = A[(size_t)row*lda+gk+2];
                }
                if (lnmode) {
                    float mean = sMean[m], rstd = sRstd[m];
                    float4 w4 = *reinterpret_cast<const float4*>(&lnw[gk]);
                    float4 b4 = *reinterpret_cast<const float4*>(&lnb[gk]);
                    v.x = (v.x - mean)*rstd*w4.x + b4.x;
                    v.y = (v.y - mean)*rstd*w4.y + b4.y;
                    v.z = (v.z - mean)*rstd*w4.z + b4.z;
                    v.w = (v.w - mean)*rstd*w4.w + b4.w;
                }
            }
            rA[i] = v;
        }
        #pragma unroll
        for (int i = 0; i < NW4; i++) {
            int slot = tid + i*T;
            int gn = n0 + (slot >> 2), gk = k0 + (slot & 3)*4;
            float4 v = make_float4(0.f,0.f,0.f,0.f);
            if (gn < N && gk < K) {
                if (gk + 3 < K) v = *reinterpret_cast<const float4*>(&W[(size_t)gn*ldw + gk]);
                else {
                    v.x = W[(size_t)gn*ldw+gk];
                    if (gk+1 < K) v.y = W[(size_t)gn*ldw+gk+1];
                    if (gk+2 < K) v.z = W[(size_t)gn*ldw+gk+2];
                }
            }
            rW[i] = v;
        }
    };
    auto store_tile = [&](int s) {
        #pragma unroll
        for (int i = 0; i < NA4; i++) {
            int slot = tid + i*T;
            int m = slot >> 2, kw = (slot & 3)*2;
            float4 v = rA[i];
            uint32_t h0 = packbf(v.x, v.y), h1 = packbf(v.z, v.w);
            __nv_bfloat162 b0 = *reinterpret_cast<__nv_bfloat162*>(&h0);
            __nv_bfloat162 b1 = *reinterpret_cast<__nv_bfloat162*>(&h1);
            ASH(s,m,kw)   = h0; ASH(s,m,kw+1) = h1;
            ASL(s,m,kw)   = packbf(v.x - __low2float(b0), v.y - __high2float(b0));
            ASL(s,m,kw+1) = packbf(v.z - __low2float(b1), v.w - __high2float(b1));
        }
        #pragma unroll
        for (int i = 0; i < NW4; i++) {
            int slot = tid + i*T;
            int n = slot >> 2, kw = (slot & 3)*2;
            float4 v = rW[i];
            uint32_t h0 = packbf(v.x, v.y), h1 = packbf(v.z, v.w);
            __nv_bfloat162 b0 = *reinterpret_cast<__nv_bfloat162*>(&h0);
            __nv_bfloat162 b1 = *reinterpret_cast<__nv_bfloat162*>(&h1);
            WSH(s,n,kw)   = h0; WSH(s,n,kw+1) = h1;
            WSL(s,n,kw)   = packbf(v.x - __low2float(b0), v.y - __high2float(b0));
            WSL(s,n,kw+1) = packbf(v.z - __low2float(b1), v.w - __high2float(b1));
        }
    };

    int nt = (K + TBK - 1) / TBK;
    load_tile(0);
    store_tile(0);
    __syncthreads();

    for (int it = 0; it < nt; it++) {
        int cur = it & 1;
        if (it + 1 < nt) load_tile((it+1) * TBK);
        uint32_t ah[2][4], al[2][4], bh[4][2], bl[4][2];
        #pragma unroll
        for (int mf = 0; mf < 2; mf++) {
            int mr = wm*32 + mf*16;
            ah[mf][0] = ASH(cur, mr + g,     t    );
            ah[mf][1] = ASH(cur, mr + 8 + g, t    );
            ah[mf][2] = ASH(cur, mr + g,     t + 4);
            ah[mf][3] = ASH(cur, mr + 8 + g, t + 4);
            al[mf][0] = ASL(cur, mr + g,     t    );
            al[mf][1] = ASL(cur, mr + 8 + g, t    );
            al[mf][2] = ASL(cur, mr + g,     t + 4);
            al[mf][3] = ASL(cur, mr + 8 + g, t + 4);
        }
        #pragma unroll
        for (int nf = 0; nf < 4; nf++) {
            int nr = wn*32 + nf*8;
            bh[nf][0] = WSH(cur, nr + g, t    );
            bh[nf][1] = WSH(cur, nr + g, t + 4);
            bl[nf][0] = WSL(cur, nr + g, t    );
            bl[nf][1] = WSL(cur, nr + g, t + 4);
        }
        #pragma unroll
        for (int mf = 0; mf < 2; mf++)
            #pragma unroll
            for (int nf = 0; nf < 4; nf++) {
                mma16(acc[mf][nf], al[mf], bh[nf]);   // lo*hi
                mma16(acc[mf][nf], ah[mf], bl[nf]);   // hi*lo
                mma16(acc[mf][nf], ah[mf], bh[nf]);   // hi*hi
            }
        if (it + 1 < nt) store_tile(cur ^ 1);
        __syncthreads();
    }

    // ---- epilogue ----
    if (mode == 3 && n0 < DI) {
        // fused causal depthwise conv + silu (BM=128: full sequence in tile)
        float* cb = reinterpret_cast<float*>(smem);   // [128][68] reuse
        #pragma unroll
        for (int mf = 0; mf < 2; mf++)
            #pragma unroll
            for (int nf = 0; nf < 4; nf++)
                #pragma unroll
                for (int e = 0; e < 4; e++) {
                    int r = wm*32 + mf*16 + g + (e >> 1) * 8;
                    int c = wn*32 + nf*8 + 2*t + (e & 1);
                    cb[r*68 + c] = acc[mf][nf][e];
                }
        __syncthreads();
        int b = blockIdx.y;   // replica
        for (int idx = tid; idx < 128*TBN; idx += T) {
            int tt = idx >> 6, c = idx & 63;
            int ch = n0 + c;
            float s = cvb[ch];
            #pragma unroll
            for (int k = 0; k < DC; k++) {
                int tp = tt - (DC-1) + k;
                if (tp >= 0) s += cb[tp*68 + c] * cvw[ch*DC + k];
            }
            uout[(size_t)((b<<7)+tt)*DI + ch] = siluf(s);
        }
        return;
    }
    #pragma unroll
    for (int mf = 0; mf < 2; mf++) {
        #pragma unroll
        for (int nf = 0; nf < 4; nf++) {
            #pragma unroll
            for (int e = 0; e < 4; e++) {
                int gm = m0 + wm*32 + mf*16 + g + (e >> 1) * 8;
                int gn = n0 + wn*32 + nf*8 + 2*t + (e & 1);
                if (gm < M && gn < N) {
                    float v = acc[mf][nf][e];
                    if (bias) v += bias[gn];
                    if (act == 1) v = softplusf(v);
                    if (mode == 0)      C[(size_t)gm*ldc + gn] = v;
                    else if (mode == 1) C[(size_t)gm*ldc + gn] += v;
                    else if (mode == 2) {
                        int l = gm >> 4, n = gm & 15;
                        C[(size_t)((n<<7)+l)*ldc + gn] += v;
                    } else {            // mode 3, z half
                        zout[(size_t)gm*DI + (gn - DI)] = v;
                    }
                }
            }
        }
    }
}

// selective scan + fused dt-proj + fused gate.
// grid (DI/32, NREP), block 512: tid = s + 16*dl for scan phase.
__global__ void k_scan2(const float* __restrict__ A_log, const float* __restrict__ skipD,
                        const float* __restrict__ dpw, const float* __restrict__ dpb) {
    __shared__ float sdt[LSEQ][32];  // computed dt; recycled as y buffer
    __shared__ float su [LSEQ][32];
    __shared__ float sB [LSEQ][DS];
    __shared__ float sC [LSEQ][DS];
    __shared__ float sX [LSEQ][DTR];
    __shared__ float sW [32][DTR+1];
    int b = blockIdx.y, dchunk = blockIdx.x;
    int tid = threadIdx.x;
    const size_t slab = (size_t)ROWS * XDW;
    // preload u
    for (int idx = tid; idx < LSEQ*32; idx += 512) {
        int tt = idx >> 5, dd = idx & 31;
        int row = (b<<7) + tt;
        su[tt][dd] = g_u[(size_t)row*DI + dchunk*32 + dd];
    }
    // xdbl = sum of split-K partials
    for (int idx = tid; idx < LSEQ*DTR; idx += 512) {
        int tt = idx >> 4, kk = idx & 15;
        size_t base = (size_t)((b<<7) + tt)*XDW;
        float vx = 0.f, vb = 0.f, vc = 0.f;
        #pragma unroll
        for (int sl = 0; sl < KSPLIT; sl++) {
            vx += g_xdbl[sl*slab + base + kk];
            vb += g_xdbl[sl*slab + base + DTR + kk];
            vc += g_xdbl[sl*slab + base + DTR + DS + kk];
        }
        sX[tt][kk] = vx;
        sB[tt][kk] = vb;
        sC[tt][kk] = vc;
    }
    // dt-proj weight slice
    if (tid < 32*DTR) {
        int dd = tid >> 4, kk = tid & 15;
        sW[dd][kk] = dpw[(dchunk*32 + dd)*DTR + kk];
    }
    __syncthreads();
    // dt = softplus(sX @ sW^T + dpb)
    for (int idx = tid; idx < LSEQ*32; idx += 512) {
        int tt = idx >> 5, dd = idx & 31;
        float a = dpb[dchunk*32 + dd];
        #pragma unroll
        for (int kk = 0; kk < DTR; kk++) a += sX[tt][kk] * sW[dd][kk];
        sdt[tt][dd] = softplusf(a);
    }
    __syncthreads();
    int s = tid & 15, dl = tid >> 4;         // dl 0..31
    int d = dchunk*32 + dl;
    float Ads = -__expf(A_log[d*DS + s]);
    float skip = skipD[d];
    float h = 0.f;
    for (int t = 0; t < LSEQ; t++) {
        float dtv = sdt[t][dl], uv = su[t][dl];
        h = __expf(dtv*Ads)*h + dtv*uv*sB[t][s];
        float p = h * sC[t][s];
        p += __shfl_xor_sync(0xffffffffu, p, 8, 16);
        p += __shfl_xor_sync(0xffffffffu, p, 4, 16);
        p += __shfl_xor_sync(0xffffffffu, p, 2, 16);
        p += __shfl_xor_sync(0xffffffffu, p, 1, 16);
        if (s == 0) sdt[t][dl] = p + uv * skip;   // recycle sdt as y
    }
    __syncthreads();
    // fused gate: gate = y * silu(z)
    for (int idx = tid; idx < LSEQ*32; idx += 512) {
        int tt = idx >> 5, dd = idx & 31;
        int row = (b<<7) + tt;
        int gd = dchunk*32 + dd;
        float z = g_z[(size_t)row*DI + gd];
        g_gate[(size_t)row*DI + gd] = sdt[tt][dd] * siluf(z);
    }
}

// attention over the 16 replicas at each position l. grid=128, block=256.
__global__ void k_attn() {
    __shared__ float sK[NREP][DMODEL];
    __shared__ float sV[NREP][DMODEL];
    __shared__ float sS[NH][NREP][NREP];
    int l = blockIdx.x;
    int tid = threadIdx.x;
    for (int idx = tid; idx < NREP*DMODEL; idx += 256) {
        int n = idx >> 8, d = idx & (DMODEL-1);
        size_t base = (size_t)((l<<4)+n)*(3*DMODEL);
        sK[n][d] = g_qkv[base + DMODEL + d];
        sV[n][d] = g_qkv[base + 2*DMODEL + d];
    }
    __syncthreads();
    for (int idx = tid; idx < NH*NREP*NREP; idx += 256) {
        int h = idx >> 8;
        int i = (idx >> 4) & 15;
        int j = idx & 15;
        const float* q = &g_qkv[(size_t)((l<<4)+i)*(3*DMODEL) + h*HD];
        float dot = 0.f;
        #pragma unroll 8
        for (int dh = 0; dh < HD; dh++) dot += q[dh] * sK[j][h*HD + dh];
        sS[h][i][j] = dot * 0.125f;
    }
    __syncthreads();
    if (tid < NH*NREP) {
        int h = tid >> 4, i = tid & 15;
        float mx = -1e30f;
        #pragma unroll
        for (int j = 0; j < NREP; j++) mx = fmaxf(mx, sS[h][i][j]);
        float sum = 0.f;
        #pragma unroll
        for (int j = 0; j < NREP; j++) { float e = __expf(sS[h][i][j]-mx); sS[h][i][j] = e; sum += e; }
        float inv = 1.f/sum;
        #pragma unroll
        for (int j = 0; j < NREP; j++) sS[h][i][j] *= inv;
    }
    __syncthreads();
    for (int idx = tid; idx < NREP*DMODEL; idx += 256) {
        int i = idx >> 8, d = idx & (DMODEL-1);
        int h = d >> 6;
        float o = 0.f;
        #pragma unroll
        for (int j = 0; j < NREP; j++) o += sS[h][i][j] * sV[j][d];
        g_attno[(size_t)((l<<4)+i)*DMODEL + d] = o;
    }
}

// ---------------- launch ----------
extern "C" void kernel_launch(void* const* d_in, const int* in_sizes, int n_in,
                              void* d_out, int out_size) {
    const int*   x     = (const int*)  d_in[0];
    const float* emb   = (const float*)d_in[1];
    const float* n1w   = (const float*)d_in[2];
    const float* n1b   = (const float*)d_in[3];
    const float* n2w   = (const float*)d_in[4];
    const float* n2b   = (const float*)d_in[5];
    const float* ipw   = (const float*)d_in[6];
    const float* cw    = (const float*)d_in[7];
    const float* cb    = (const float*)d_in[8];
    const float* xpw   = (const float*)d_in[9];
    const float* dpw   = (const float*)d_in[10];
    const float* dpb   = (const float*)d_in[11];
    const float* alog  = (const float*)d_in[12];
    const float* dskip = (const float*)d_in[13];
    const float* opw   = (const float*)d_in[14];
    const float* aiw   = (const float*)d_in[15];
    const float* aib   = (const float*)d_in[16];
    const float* aow   = (const float*)d_in[17];
    const float* aob   = (const float*)d_in[18];
    const float* nfw   = (const float*)d_in[19];
    const float* nfb   = (const float*)d_in[20];
    const float* headb = (const float*)d_in[21];
    float* out = (float*)d_out;

    float* ph;    cudaGetSymbolAddress((void**)&ph, g_h);
    float* pz;    cudaGetSymbolAddress((void**)&pz, g_z);
    float* pu;    cudaGetSymbolAddress((void**)&pu, g_u);
    float* pxdbl; cudaGetSymbolAddress((void**)&pxdbl, g_xdbl);
    float* pgate; cudaGetSymbolAddress((void**)&pgate, g_gate);
    float* pqkv;  cudaGetSymbolAddress((void**)&pqkv, g_qkv);
    float* pattno;cudaGetSymbolAddress((void**)&pattno, g_attno);
    float* phf;   cudaGetSymbolAddress((void**)&phf, g_hf);

    k_embed<<<(ROWS*DMODEL+255)/256, 256>>>(x, emb);

    for (int i = 0; i < NLAYER; i++) {
        const float* L_n1w = n1w + i*DMODEL;
        const float* L_n1b = n1b + i*DMODEL;
        const float* L_n2w = n2w + i*DMODEL;
        const float* L_n2b = n2b + i*DMODEL;
        const float* L_ipw = ipw + (size_t)i*2*DI*DMODEL;
        const float* L_cw  = cw  + (size_t)i*DI*DC;
        const float* L_cb  = cb  + (size_t)i*DI;
        const float* L_xpw = xpw + (size_t)i*XDW*DI;
        const float* L_dpw = dpw + (size_t)i*DI*DTR;
        const float* L_dpb = dpb + (size_t)i*DI;
        const float* L_alog= alog+ (size_t)i*DI*DS;
        const float* L_skip= dskip+(size_t)i*DI;
        const float* L_opw = opw + (size_t)i*DMODEL*DI;
        const float* L_aiw = aiw + (size_t)i*3*DMODEL*DMODEL;
        const float* L_aib = aib + (size_t)i*3*DMODEL;
        const float* L_aow = aow + (size_t)i*DMODEL*DMODEL;
        const float* L_aob = aob + (size_t)i*DMODEL;

        // --- mamba branch ---
        // in_proj (LN fused in prologue) + fused conv+silu (u) / z store
        k_gemm_tc<128><<<dim3((2*DI)/TBN, ROWS/128), 256>>>(
            ph, DMODEL, L_ipw, DMODEL, nullptr, nullptr, 0,
            ROWS, 2*DI, DMODEL, 0, 3, L_n1w, L_n1b, 1, L_cw, L_cb, pu, pz);
        // xdbl partials = u @ xpw^T, split-K x4
        k_gemm_tc<64><<<dim3(1, ROWS/64, KSPLIT), 128>>>(
            pu, DI, L_xpw, DI, nullptr, pxdbl, XDW,
            ROWS, XDW, DI/KSPLIT, 0, 0, nullptr, nullptr, 0,
            nullptr, nullptr, nullptr, nullptr);
        // scan (+dt-proj, +gate)
        k_scan2<<<dim3(DI/32, NREP), 512>>>(L_alog, L_skip, L_dpw, L_dpb);
        // h += gate @ opw^T
        k_gemm_tc<64><<<dim3(DMODEL/TBN, ROWS/64), 128>>>(
            pgate, DI, L_opw, DI, nullptr, ph, DMODEL,
            ROWS, DMODEL, DI, 0, 1, nullptr, nullptr, 0,
            nullptr, nullptr, nullptr, nullptr);
        // --- attention branch ---
        // qkv (LN2 fused, permuted read)
        k_gemm_tc<128><<<dim3((3*DMODEL)/TBN, ROWS/128), 256>>>(
            ph, DMODEL, L_aiw, DMODEL, L_aib, pqkv, 3*DMODEL,
            ROWS, 3*DMODEL, DMODEL, 0, 0, L_n2w, L_n2b, 2,
            nullptr, nullptr, nullptr, nullptr);
        k_attn<<<LSEQ, 256>>>();
        k_gemm_tc<64><<<dim3(DMODEL/TBN, ROWS/64), 128>>>(
            pattno, DMODEL, L_aow, DMODEL, L_aob, ph, DMODEL,
            ROWS, DMODEL, DMODEL, 0, 2, nullptr, nullptr, 0,
            nullptr, nullptr, nullptr, nullptr);
    }

    k_meanln<<<LSEQ, 256>>>(nfw, nfb);
    k_gemm_tc<128><<<dim3(VOCAB/TBN, 1), 256>>>(
        phf, DMODEL, emb, DMODEL, headb, out, VOCAB,
        LSEQ, VOCAB, DMODEL, 0, 0, nullptr, nullptr, 0,
        nullptr, nullptr, nullptr, nullptr);
}

// round 8
// speedup vs baseline: 1.4345x; 1.4345x over previous
#include <cuda_runtime.h>
#include <cuda_bf16.h>
#include <cstdint>
#include <math.h>

#define VOCAB 32000
#define DMODEL 256
#define NLAYER 6
#define DS 16
#define DC 4
#define DI 512
#define DTR 16
#define LSEQ 128
#define XDW 48             // DTR + 2*DS
#define KSPLIT 4

// All 16 replicas are provably identical (replica-symmetric network); we
// compute one. Rows = LSEQ = 128.

// ---------------- scratch (device globals; no allocation allowed) ----------
__device__ float g_h[LSEQ*DMODEL];          // residual stream [l, 256]
__device__ float g_z[LSEQ*DI];              // z half of in_proj
__device__ float g_u[LSEQ*DI];              // conv+silu out
__device__ float g_xdbl[KSPLIT*LSEQ*XDW];   // split-K partials of u @ xpw^T
__device__ float g_gate[LSEQ*DI];           // y * silu(z)
__device__ float g_v[LSEQ*DMODEL];          // attention value (== attn output)
__device__ float g_hf[LSEQ*DMODEL];         // final LN

// ---------------- helpers ----------
__device__ __forceinline__ float siluf(float x) {
    return x / (1.f + __expf(-x));
}
__device__ __forceinline__ float softplusf(float x) {
    return (x > 20.f) ? x : log1pf(__expf(x));
}

__device__ __forceinline__ uint32_t packbf(float x, float y) {
    __nv_bfloat162 h = __floats2bfloat162_rn(x, y);
    return *reinterpret_cast<uint32_t*>(&h);
}

// bf16 m16n8k16 mma, fp32 accumulate
__device__ __forceinline__ void mma16(float* c, const uint32_t* a, const uint32_t* b) {
    asm volatile(
        "mma.sync.aligned.m16n8k16.row.col.f32.bf16.bf16.f32 "
        "{%0,%1,%2,%3}, {%4,%5,%6,%7}, {%8,%9}, {%0,%1,%2,%3};"
        : "+f"(c[0]), "+f"(c[1]), "+f"(c[2]), "+f"(c[3])
        : "r"(a[0]), "r"(a[1]), "r"(a[2]), "r"(a[3]), "r"(b[0]), "r"(b[1]));
}

__device__ float blockReduceSum256(float v) {
    __shared__ float s[8];
    __shared__ float tot;
    int lane = threadIdx.x & 31, wid = threadIdx.x >> 5;
    #pragma unroll
    for (int o = 16; o > 0; o >>= 1) v += __shfl_xor_sync(0xffffffffu, v, o);
    if (lane == 0) s[wid] = v;
    __syncthreads();
    if (wid == 0) {
        float w = (lane < 8) ? s[lane] : 0.f;
        #pragma unroll
        for (int o = 4; o > 0; o >>= 1) w += __shfl_xor_sync(0xffffffffu, w, o);
        if (lane == 0) tot = w;
    }
    __syncthreads();
    float r = tot;
    __syncthreads();
    return r;
}

// ---------------- kernels ----------

__global__ void k_embed(const int* __restrict__ x, const float* __restrict__ emb) {
    int idx = blockIdx.x * blockDim.x + threadIdx.x;       // 128*256
    if (idx >= LSEQ*DMODEL) return;
    int d = idx & (DMODEL-1);
    int l = idx >> 8;
    g_h[idx] = emb[(size_t)x[l]*DMODEL + d];
}

// final LayerNorm. grid = LSEQ, block = 256.
__global__ void k_ln(const float* __restrict__ w, const float* __restrict__ b) {
    int l = blockIdx.x;
    int d = threadIdx.x;
    float v = g_h[(size_t)l*DMODEL + d];
    float m = blockReduceSum256(v) * (1.f/DMODEL);
    float c = v - m;
    float var = blockReduceSum256(c*c) * (1.f/DMODEL);
    g_hf[(size_t)l*DMODEL + d] = c * rsqrtf(var + 1e-5f) * w[d] + b[d];
}

// ---------------- tensor-core split-bf16 GEMM (near-fp32 accurate) --------
// C[M,N] = act(A[M,K] @ W[N,K]^T + bias)
// mode: 0 = store, 1 = +=
// mode 3 = in_proj special (BM=128): n0<DI -> fused causal conv+silu -> uout;
//          n0>=DI -> store z half to zout (compact DI-wide).
// lnmode: 1 = LayerNorm A rows in prologue (K must equal LN dim).
// split-K: gridDim.z>1 shifts A,W by z*K cols and C by z*M*ldc.
#define TBN 64
#define TBK 16
#define SW 12           // padded words per row (8 data + 4 pad)
template<int BM>
__global__ void __launch_bounds__(BM*2)
k_gemm_tc(const float* __restrict__ A, int lda,
          const float* __restrict__ W, int ldw,
          const float* __restrict__ bias,
          float* __restrict__ C, int ldc,
          int M, int N, int K, int act, int mode,
          const float* __restrict__ lnw, const float* __restrict__ lnb, int lnmode,
          const float* __restrict__ cvw, const float* __restrict__ cvb,
          float* __restrict__ uout, float* __restrict__ zout) {
    constexpr int T = BM*2;                  // 256 or 128 threads
    constexpr int AW = 2*BM*SW;
    constexpr int WW = 2*TBN*SW;
    __shared__ __align__(16) uint32_t smem[2*AW + 2*WW];
    __shared__ float sMean[BM], sRstd[BM];
    uint32_t* Ash = smem;
    uint32_t* Asl = smem + AW;
    uint32_t* Wsh = smem + 2*AW;
    uint32_t* Wsl = smem + 2*AW + WW;
    #define ASH(s,m,k) Ash[((s)*BM+(m))*SW+(k)]
    #define ASL(s,m,k) Asl[((s)*BM+(m))*SW+(k)]
    #define WSH(s,n,k) Wsh[((s)*TBN+(n))*SW+(k)]
    #define WSL(s,n,k) Wsl[((s)*TBN+(n))*SW+(k)]

    int tid = threadIdx.x;
    int wid = tid >> 5, lane = tid & 31;
    int wm = wid >> 1, wn = wid & 1;
    int g = lane >> 2, t = lane & 3;
    int m0 = blockIdx.y * BM, n0 = blockIdx.x * TBN;

    // split-K offsets
    if (gridDim.z > 1) {
        A += (size_t)blockIdx.z * K;
        W += (size_t)blockIdx.z * K;
        C += (size_t)blockIdx.z * M * ldc;
    }

    // optional LN prologue: row stats for this block's BM rows
    if (lnmode) {
        constexpr int NWARP = T/32;
        for (int r = wid; r < BM; r += NWARP) {
            int gm = m0 + r;
            float s = 0.f, s2 = 0.f;
            for (int k = lane*4; k < K; k += 128) {
                float4 v = *reinterpret_cast<const float4*>(&A[(size_t)gm*lda + k]);
                s  += v.x + v.y + v.z + v.w;
                s2 += v.x*v.x + v.y*v.y + v.z*v.z + v.w*v.w;
            }
            #pragma unroll
            for (int o = 16; o > 0; o >>= 1) {
                s  += __shfl_xor_sync(0xffffffffu, s, o);
                s2 += __shfl_xor_sync(0xffffffffu, s2, o);
            }
            if (lane == 0) {
                float mean = s / K;
                float var = s2 / K - mean*mean;
                sMean[r] = mean;
                sRstd[r] = rsqrtf(var + 1e-5f);
            }
        }
        __syncthreads();
    }

    float acc[2][4][4] = {};
    constexpr int NA4 = BM*4/T;   // per-thread A float4 count (=2)
    constexpr int NW4 = TBN*4/T;  // per-thread W float4 count (1 or 2)
    float4 rA[NA4], rW[NW4 ? NW4 : 1];

    auto load_tile = [&](int k0) {
        #pragma unroll
        for (int i = 0; i < NA4; i++) {
            int slot = tid + i*T;
            int m = slot >> 2;
            int gm = m0 + m, gk = k0 + (slot & 3)*4;
            float4 v = make_float4(0.f,0.f,0.f,0.f);
            if (gm < M && gk < K) {
                if (gk + 3 < K) v = *reinterpret_cast<const float4*>(&A[(size_t)gm*lda + gk]);
                else {
                    v.x = A[(size_t)gm*lda+gk];
                    if (gk+1 < K) v.y = A[(size_t)gm*lda+gk+1];
                    if (gk+2 < K) v.z = A[(size_t)gm*lda+gk+2];
                }
                if (lnmode) {
                    float mean = sMean[m], rstd = sRstd[m];
                    float4 w4 = *reinterpret_cast<const float4*>(&lnw[gk]);
                    float4 b4 = *reinterpret_cast<const float4*>(&lnb[gk]);
                    v.x = (v.x - mean)*rstd*w4.x + b4.x;
                    v.y = (v.y - mean)*rstd*w4.y + b4.y;
                    v.z = (v.z - mean)*rstd*w4.z + b4.z;
                    v.w = (v.w - mean)*rstd*w4.w + b4.w;
                }
            }
            rA[i] = v;
        }
        #pragma unroll
        for (int i = 0; i < NW4; i++) {
            int slot = tid + i*T;
            int gn = n0 + (slot >> 2), gk = k0 + (slot & 3)*4;
            float4 v = make_float4(0.f,0.f,0.f,0.f);
            if (gn < N && gk < K) {
                if (gk + 3 < K) v = *reinterpret_cast<const float4*>(&W[(size_t)gn*ldw + gk]);
                else {
                    v.x = W[(size_t)gn*ldw+gk];
                    if (gk+1 < K) v.y = W[(size_t)gn*ldw+gk+1];
                    if (gk+2 < K) v.z = W[(size_t)gn*ldw+gk+2];
                }
            }
            rW[i] = v;
        }
    };
    auto store_tile = [&](int s) {
        #pragma unroll
        for (int i = 0; i < NA4; i++) {
            int slot = tid + i*T;
            int m = slot >> 2, kw = (slot & 3)*2;
            float4 v = rA[i];
            uint32_t h0 = packbf(v.x, v.y), h1 = packbf(v.z, v.w);
            __nv_bfloat162 b0 = *reinterpret_cast<__nv_bfloat162*>(&h0);
            __nv_bfloat162 b1 = *reinterpret_cast<__nv_bfloat162*>(&h1);
            ASH(s,m,kw)   = h0; ASH(s,m,kw+1) = h1;
            ASL(s,m,kw)   = packbf(v.x - __low2float(b0), v.y - __high2float(b0));
            ASL(s,m,kw+1) = packbf(v.z - __low2float(b1), v.w - __high2float(b1));
        }
        #pragma unroll
        for (int i = 0; i < NW4; i++) {
            int slot = tid + i*T;
            int n = slot >> 2, kw = (slot & 3)*2;
            float4 v = rW[i];
            uint32_t h0 = packbf(v.x, v.y), h1 = packbf(v.z, v.w);
            __nv_bfloat162 b0 = *reinterpret_cast<__nv_bfloat162*>(&h0);
            __nv_bfloat162 b1 = *reinterpret_cast<__nv_bfloat162*>(&h1);
            WSH(s,n,kw)   = h0; WSH(s,n,kw+1) = h1;
            WSL(s,n,kw)   = packbf(v.x - __low2float(b0), v.y - __high2float(b0));
            WSL(s,n,kw+1) = packbf(v.z - __low2float(b1), v.w - __high2float(b1));
        }
    };

    int nt = (K + TBK - 1) / TBK;
    load_tile(0);
    store_tile(0);
    __syncthreads();

    for (int it = 0; it < nt; it++) {
        int cur = it & 1;
        if (it + 1 < nt) load_tile((it+1) * TBK);
        uint32_t ah[2][4], al[2][4], bh[4][2], bl[4][2];
        #pragma unroll
        for (int mf = 0; mf < 2; mf++) {
            int mr = wm*32 + mf*16;
            ah[mf][0] = ASH(cur, mr + g,     t    );
            ah[mf][1] = ASH(cur, mr + 8 + g, t    );
            ah[mf][2] = ASH(cur, mr + g,     t + 4);
            ah[mf][3] = ASH(cur, mr + 8 + g, t + 4);
            al[mf][0] = ASL(cur, mr + g,     t    );
            al[mf][1] = ASL(cur, mr + 8 + g, t    );
            al[mf][2] = ASL(cur, mr + g,     t + 4);
            al[mf][3] = ASL(cur, mr + 8 + g, t + 4);
        }
        #pragma unroll
        for (int nf = 0; nf < 4; nf++) {
            int nr = wn*32 + nf*8;
            bh[nf][0] = WSH(cur, nr + g, t    );
            bh[nf][1] = WSH(cur, nr + g, t + 4);
            bl[nf][0] = WSL(cur, nr + g, t    );
            bl[nf][1] = WSL(cur, nr + g, t + 4);
        }
        #pragma unroll
        for (int mf = 0; mf < 2; mf++)
            #pragma unroll
            for (int nf = 0; nf < 4; nf++) {
                mma16(acc[mf][nf], al[mf], bh[nf]);   // lo*hi
                mma16(acc[mf][nf], ah[mf], bl[nf]);   // hi*lo
                mma16(acc[mf][nf], ah[mf], bh[nf]);   // hi*hi
            }
        if (it + 1 < nt) store_tile(cur ^ 1);
        __syncthreads();
    }

    // ---- epilogue ----
    if (mode == 3 && n0 < DI) {
        // fused causal depthwise conv + silu (BM=128: full sequence in tile)
        float* cb = reinterpret_cast<float*>(smem);   // [128][68] reuse
        #pragma unroll
        for (int mf = 0; mf < 2; mf++)
            #pragma unroll
            for (int nf = 0; nf < 4; nf++)
                #pragma unroll
                for (int e = 0; e < 4; e++) {
                    int r = wm*32 + mf*16 + g + (e >> 1) * 8;
                    int c = wn*32 + nf*8 + 2*t + (e & 1);
                    cb[r*68 + c] = acc[mf][nf][e];
                }
        __syncthreads();
        for (int idx = tid; idx < 128*TBN; idx += T) {
            int tt = idx >> 6, c = idx & 63;
            int ch = n0 + c;
            float s = cvb[ch];
            #pragma unroll
            for (int k = 0; k < DC; k++) {
                int tp = tt - (DC-1) + k;
                if (tp >= 0) s += cb[tp*68 + c] * cvw[ch*DC + k];
            }
            uout[(size_t)tt*DI + ch] = siluf(s);
        }
        return;
    }
    #pragma unroll
    for (int mf = 0; mf < 2; mf++) {
        #pragma unroll
        for (int nf = 0; nf < 4; nf++) {
            #pragma unroll
            for (int e = 0; e < 4; e++) {
                int gm = m0 + wm*32 + mf*16 + g + (e >> 1) * 8;
                int gn = n0 + wn*32 + nf*8 + 2*t + (e & 1);
                if (gm < M && gn < N) {
                    float v = acc[mf][nf][e];
                    if (bias) v += bias[gn];
                    if (act == 1) v = softplusf(v);
                    if (mode == 0)      C[(size_t)gm*ldc + gn] = v;
                    else if (mode == 1) C[(size_t)gm*ldc + gn] += v;
                    else {              // mode 3, z half
                        zout[(size_t)gm*DI + (gn - DI)] = v;
                    }
                }
            }
        }
    }
}

// selective scan + fused dt-proj + fused gate.
// grid (DI/32, 1), block 512: tid = s + 16*dl for scan phase.
__global__ void k_scan2(const float* __restrict__ A_log, const float* __restrict__ skipD,
                        const float* __restrict__ dpw, const float* __restrict__ dpb) {
    __shared__ float sdt[LSEQ][32];  // computed dt; recycled as y buffer
    __shared__ float su [LSEQ][32];
    __shared__ float sB [LSEQ][DS];
    __shared__ float sC [LSEQ][DS];
    __shared__ float sX [LSEQ][DTR];
    __shared__ float sW [32][DTR+1];
    int dchunk = blockIdx.x;
    int tid = threadIdx.x;
    const size_t slab = (size_t)LSEQ * XDW;
    // preload u
    for (int idx = tid; idx < LSEQ*32; idx += 512) {
        int tt = idx >> 5, dd = idx & 31;
        su[tt][dd] = g_u[(size_t)tt*DI + dchunk*32 + dd];
    }
    // xdbl = sum of split-K partials
    for (int idx = tid; idx < LSEQ*DTR; idx += 512) {
        int tt = idx >> 4, kk = idx & 15;
        size_t base = (size_t)tt*XDW;
        float vx = 0.f, vb = 0.f, vc = 0.f;
        #pragma unroll
        for (int sl = 0; sl < KSPLIT; sl++) {
            vx += g_xdbl[sl*slab + base + kk];
            vb += g_xdbl[sl*slab + base + DTR + kk];
            vc += g_xdbl[sl*slab + base + DTR + DS + kk];
        }
        sX[tt][kk] = vx;
        sB[tt][kk] = vb;
        sC[tt][kk] = vc;
    }
    // dt-proj weight slice
    if (tid < 32*DTR) {
        int dd = tid >> 4, kk = tid & 15;
        sW[dd][kk] = dpw[(dchunk*32 + dd)*DTR + kk];
    }
    __syncthreads();
    // dt = softplus(sX @ sW^T + dpb)
    for (int idx = tid; idx < LSEQ*32; idx += 512) {
        int tt = idx >> 5, dd = idx & 31;
        float a = dpb[dchunk*32 + dd];
        #pragma unroll
        for (int kk = 0; kk < DTR; kk++) a += sX[tt][kk] * sW[dd][kk];
        sdt[tt][dd] = softplusf(a);
    }
    __syncthreads();
    int s = tid & 15, dl = tid >> 4;         // dl 0..31
    int d = dchunk*32 + dl;
    float Ads = -__expf(A_log[d*DS + s]);
    float skip = skipD[d];
    float h = 0.f;
    for (int t = 0; t < LSEQ; t++) {
        float dtv = sdt[t][dl], uv = su[t][dl];
        h = __expf(dtv*Ads)*h + dtv*uv*sB[t][s];
        float p = h * sC[t][s];
        p += __shfl_xor_sync(0xffffffffu, p, 8, 16);
        p += __shfl_xor_sync(0xffffffffu, p, 4, 16);
        p += __shfl_xor_sync(0xffffffffu, p, 2, 16);
        p += __shfl_xor_sync(0xffffffffu, p, 1, 16);
        if (s == 0) sdt[t][dl] = p + uv * skip;   // recycle sdt as y
    }
    __syncthreads();
    // fused gate: gate = y * silu(z)
    for (int idx = tid; idx < LSEQ*32; idx += 512) {
        int tt = idx >> 5, dd = idx & 31;
        int gd = dchunk*32 + dd;
        float z = g_z[(size_t)tt*DI + gd];
        g_gate[(size_t)tt*DI + gd] = sdt[tt][dd] * siluf(z);
    }
}

// ---------------- launch ----------
extern "C" void kernel_launch(void* const* d_in, const int* in_sizes, int n_in,
                              void* d_out, int out_size) {
    const int*   x     = (const int*)  d_in[0];
    const float* emb   = (const float*)d_in[1];
    const float* n1w   = (const float*)d_in[2];
    const float* n1b   = (const float*)d_in[3];
    const float* n2w   = (const float*)d_in[4];
    const float* n2b   = (const float*)d_in[5];
    const float* ipw   = (const float*)d_in[6];
    const float* cw    = (const float*)d_in[7];
    const float* cb    = (const float*)d_in[8];
    const float* xpw   = (const float*)d_in[9];
    const float* dpw   = (const float*)d_in[10];
    const float* dpb   = (const float*)d_in[11];
    const float* alog  = (const float*)d_in[12];
    const float* dskip = (const float*)d_in[13];
    const float* opw   = (const float*)d_in[14];
    const float* aiw   = (const float*)d_in[15];
    const float* aib   = (const float*)d_in[16];
    const float* aow   = (const float*)d_in[17];
    const float* aob   = (const float*)d_in[18];
    const float* nfw   = (const float*)d_in[19];
    const float* nfb   = (const float*)d_in[20];
    const float* headb = (const float*)d_in[21];
    float* out = (float*)d_out;

    float* ph;    cudaGetSymbolAddress((void**)&ph, g_h);
    float* pz;    cudaGetSymbolAddress((void**)&pz, g_z);
    float* pu;    cudaGetSymbolAddress((void**)&pu, g_u);
    float* pxdbl; cudaGetSymbolAddress((void**)&pxdbl, g_xdbl);
    float* pgate; cudaGetSymbolAddress((void**)&pgate, g_gate);
    float* pv;    cudaGetSymbolAddress((void**)&pv, g_v);
    float* phf;   cudaGetSymbolAddress((void**)&phf, g_hf);

    k_embed<<<(LSEQ*DMODEL+255)/256, 256>>>(x, emb);

    for (int i = 0; i < NLAYER; i++) {
        const float* L_n1w = n1w + i*DMODEL;
        const float* L_n1b = n1b + i*DMODEL;
        const float* L_n2w = n2w + i*DMODEL;
        const float* L_n2b = n2b + i*DMODEL;
        const float* L_ipw = ipw + (size_t)i*2*DI*DMODEL;
        const float* L_cw  = cw  + (size_t)i*DI*DC;
        const float* L_cb  = cb  + (size_t)i*DI;
        const float* L_xpw = xpw + (size_t)i*XDW*DI;
        const float* L_dpw = dpw + (size_t)i*DI*DTR;
        const float* L_dpb = dpb + (size_t)i*DI;
        const float* L_alog= alog+ (size_t)i*DI*DS;
        const float* L_skip= dskip+(size_t)i*DI;
        const float* L_opw = opw + (size_t)i*DMODEL*DI;
        const float* L_aivw= aiw + (size_t)i*3*DMODEL*DMODEL + (size_t)2*DMODEL*DMODEL; // Wv
        const float* L_aivb= aib + (size_t)i*3*DMODEL + 2*DMODEL;                       // bv
        const float* L_aow = aow + (size_t)i*DMODEL*DMODEL;
        const float* L_aob = aob + (size_t)i*DMODEL;

        // --- mamba branch ---
        // in_proj (LN1 fused) + fused conv+silu (u) / z store
        k_gemm_tc<128><<<dim3((2*DI)/TBN, 1), 256>>>(
            ph, DMODEL, L_ipw, DMODEL, nullptr, nullptr, 0,
            LSEQ, 2*DI, DMODEL, 0, 3, L_n1w, L_n1b, 1, L_cw, L_cb, pu, pz);
        // xdbl partials = u @ xpw^T, split-K x4
        k_gemm_tc<64><<<dim3(1, LSEQ/64, KSPLIT), 128>>>(
            pu, DI, L_xpw, DI, nullptr, pxdbl, XDW,
            LSEQ, XDW, DI/KSPLIT, 0, 0, nullptr, nullptr, 0,
            nullptr, nullptr, nullptr, nullptr);
        // scan (+dt-proj, +gate)
        k_scan2<<<dim3(DI/32, 1), 512>>>(L_alog, L_skip, L_dpw, L_dpb);
        // h += gate @ opw^T
        k_gemm_tc<64><<<dim3(DMODEL/TBN, LSEQ/64), 128>>>(
            pgate, DI, L_opw, DI, nullptr, ph, DMODEL,
            LSEQ, DMODEL, DI, 0, 1, nullptr, nullptr, 0,
            nullptr, nullptr, nullptr, nullptr);
        // --- attention branch (collapses to v-proj + out-proj) ---
        // v = LN2(h) @ Wv^T + bv
        k_gemm_tc<64><<<dim3(DMODEL/TBN, LSEQ/64), 128>>>(
            ph, DMODEL, L_aivw, DMODEL, L_aivb, pv, DMODEL,
            LSEQ, DMODEL, DMODEL, 0, 0, L_n2w, L_n2b, 1,
            nullptr, nullptr, nullptr, nullptr);
        // h += v @ aow^T + aob
        k_gemm_tc<64><<<dim3(DMODEL/TBN, LSEQ/64), 128>>>(
            pv, DMODEL, L_aow, DMODEL, L_aob, ph, DMODEL,
            LSEQ, DMODEL, DMODEL, 0, 1, nullptr, nullptr, 0,
            nullptr, nullptr, nullptr, nullptr);
    }

    k_ln<<<LSEQ, 256>>>(nfw, nfb);
    k_gemm_tc<128><<<dim3(VOCAB/TBN, 1), 256>>>(
        phf, DMODEL, emb, DMODEL, headb, out, VOCAB,
        LSEQ, VOCAB, DMODEL, 0, 0, nullptr, nullptr, 0,
        nullptr, nullptr, nullptr, nullptr);
}